// round 16
// baseline (speedup 1.0000x reference)
#include <cuda_runtime.h>
#include <cstdint>

#define NG    4
#define MPTS  50000
#define CIN   64
#define KNN   9
#define OUTC  64
#define BM    128
#define NTH   256          // prepass threads
#define NTHM  512          // main kernel threads (16 warps)
#define NCHUNK 11

#define ROWB      272
#define A_BYTES   (BM * ROWB)
#define OFF_A0    0
#define OFF_A1    A_BYTES
#define OFF_IDX   (2 * A_BYTES)
#define OFF_MBAR  (OFF_IDX + BM * KNN * 4)
#define SMEM_MAIN (OFF_MBAR + 16)            // 74256 -> 2 CTAs/SM @ 512 thr

// prepass block ranges
#define NB_LOC  782
#define NB_FRG  88

// ---- persistent scratch ----
__device__ float  g_locF[(size_t)NG * MPTS * 24];      // loc features (tf32-rna)
__device__ float2 g_fragW[NCHUNK * 2048];              // W in b-fragment order (tf32-rna)

__device__ __forceinline__ float tf32r(float x) {
    uint32_t u;
    asm("cvt.rna.tf32.f32 %0, %1;" : "=r"(u) : "f"(x));
    return __uint_as_float(u);
}
__device__ __forceinline__ uint32_t tf32u(float x) {
    uint32_t u;
    asm("cvt.rna.tf32.f32 %0, %1;" : "=r"(u) : "f"(x));
    return u;
}
__device__ __forceinline__ uint32_t smem_u32(const void* p) {
    uint32_t a;
    asm("{ .reg .u64 t; cvta.to.shared.u64 t, %1; cvt.u32.u64 %0, t; }" : "=r"(a) : "l"(p));
    return a;
}
__device__ __forceinline__ void mma_tf32(float d[4],
                                         uint32_t a0, uint32_t a1, uint32_t a2, uint32_t a3,
                                         uint32_t b0, uint32_t b1) {
    asm volatile(
        "mma.sync.aligned.m16n8k8.row.col.f32.tf32.tf32.f32 "
        "{%0,%1,%2,%3}, {%4,%5,%6,%7}, {%8,%9}, {%0,%1,%2,%3};"
        : "+f"(d[0]), "+f"(d[1]), "+f"(d[2]), "+f"(d[3])
        : "r"(a0), "r"(a1), "r"(a2), "r"(a3), "r"(b0), "r"(b1));
}
__device__ __forceinline__ void mbar_wait(uint32_t mbar, uint32_t parity) {
    uint32_t done;
    asm volatile(
        "{\n\t.reg .pred p;\n\t"
        "mbarrier.try_wait.parity.acquire.cta.shared::cta.b64 p, [%1], %2;\n\t"
        "selp.b32 %0, 1, 0, p;\n\t}"
        : "=r"(done) : "r"(mbar), "r"(parity) : "memory");
    if (!done) {
        asm volatile(
            "{\n\t.reg .pred P1;\n\t"
            "W_%=:\n\t"
            "mbarrier.try_wait.parity.acquire.cta.shared::cta.b64 P1, [%0], %1, 0x989680;\n\t"
            "@P1 bra.uni D_%=;\n\t"
            "bra.uni W_%=;\n\t"
            "D_%=:\n\t}"
            :: "r"(mbar), "r"(parity) : "memory");
    }
}

// ---------------- pre-pass (loc features + W fragments) ----------------

__global__ void __launch_bounds__(NTH) k_prep(const int*   __restrict__ aff,
                                              const float* __restrict__ locs,
                                              const float* __restrict__ Wt)
{
    int b = blockIdx.x;
    if (b < NB_LOC) {
        int t = b * NTH + threadIdx.x;
        if (t >= NG * MPTS) return;
        int g = t / MPTS, m = t - g * MPTS;
        const int*   I = aff  + (size_t)g * MPTS * KNN + (size_t)m * KNN;
        const float* L = locs + (size_t)g * MPTS * 2;
        float lx = L[2 * m], ly = L[2 * m + 1];
        float o[24];
        #pragma unroll
        for (int j = 18; j < 24; j++) o[j] = 0.f;
        #pragma unroll
        for (int k = 0; k < KNN; k++) {
            int s = I[k];
            float dx = (L[2 * s]     - lx) * (1.0f / 11.0f);
            float dy = (L[2 * s + 1] - ly) * (1.0f / 11.0f);
            o[2 * k]     = tf32r(fminf(fmaxf(dx, -1.f), 1.f));
            o[2 * k + 1] = tf32r(fminf(fmaxf(dy, -1.f), 1.f));
        }
        float4* d = (float4*)(g_locF + (size_t)t * 24);
        #pragma unroll
        for (int j = 0; j < 6; j++)
            d[j] = make_float4(o[4*j], o[4*j+1], o[4*j+2], o[4*j+3]);
        return;
    }
    b -= NB_LOC;
    {
        int t = b * NTH + threadIdx.x;
        if (t >= NCHUNK * 2048) return;
        int c = t / 2048, rem = t % 2048;
        int nt = rem >> 8, ks = (rem >> 5) & 7, ln = rem & 31;
        int gq = ln >> 2, gr = ln & 3;
        int col = nt * 8 + gq;
        int k0 = ks * 8 + gr;
        int k1 = k0 + 4;
        auto krow = [&](int k) -> int {
            if (c < 9)  return c * 66 + 2 + k;
            if (c == 9) return 594 + k;
            return (k < 18) ? (k >> 1) * 66 + (k & 1) : -1;
        };
        int r0 = krow(k0), r1 = krow(k1);
        float v0 = (r0 >= 0) ? tf32r(Wt[(size_t)r0 * OUTC + col]) : 0.f;
        float v1 = (r1 >= 0) ? tf32r(Wt[(size_t)r1 * OUTC + col]) : 0.f;
        g_fragW[t] = make_float2(v0, v1);
    }
}

// ---------------- main kernel: R9 pipeline, 16 warps x (16x32) tiles ----------------

extern "C" __global__ void __launch_bounds__(NTHM, 2)
affconv_main(const float* __restrict__ feats,
             const int*   __restrict__ aff,
             const float* __restrict__ bias,
             float* __restrict__ out)
{
    extern __shared__ char smem[];
    const uint32_t sbase = smem_u32(smem);
    const int tid = threadIdx.x, lane = tid & 31, wid = tid >> 5;
    const int g = blockIdx.y, m0 = blockIdx.x * BM;
    const int gq = lane >> 2, gr = lane & 3;
    const int wr = wid >> 1, wc = wid & 1;          // 8x2 warp grid: 16 rows x 32 cols

    int* sIdx = (int*)(smem + OFF_IDX);
    const int* I = aff + (size_t)g * MPTS * KNN;

    if (tid == 0) {
        asm volatile("mbarrier.init.shared.b64 [%0], %1;" :: "r"(sbase + OFF_MBAR),     "r"(128u) : "memory");
        asm volatile("mbarrier.init.shared.b64 [%0], %1;" :: "r"(sbase + OFF_MBAR + 8), "r"(128u) : "memory");
    }
    for (int i = tid; i < BM * KNN; i += NTHM) {
        int r = i / KNN, c = i - r * KNN;
        int m = m0 + r; if (m >= MPTS) m = MPTS - 1;
        sIdx[i] = I[(size_t)m * KNN + c];
    }
    __syncthreads();

    int mrow = m0 + tid; if (mrow >= MPTS) mrow = MPTS - 1;   // valid for tid<128
    const float* featG = feats  + (size_t)g * MPTS * CIN;     // raw feats, rna in-loop
    const float* locG  = g_locF + (size_t)g * MPTS * 24;

    auto stage = [&](int c, int buf) {
        if (tid < BM) {
            uint32_t mbar = sbase + OFF_MBAR + buf * 8;
            uint32_t dst  = sbase + (buf ? OFF_A1 : OFF_A0) + tid * ROWB;
            if (c < 10) {
                asm volatile("mbarrier.arrive.expect_tx.shared.b64 _, [%0], 256;"
                             :: "r"(mbar) : "memory");
                int src = (c < 9) ? sIdx[tid * KNN + c] : mrow;
                uint64_t gp = __cvta_generic_to_global(featG + (size_t)src * CIN);
                asm volatile(
                    "cp.async.bulk.shared::cluster.global.mbarrier::complete_tx::bytes "
                    "[%0], [%1], 256, [%2];"
                    :: "r"(dst), "l"(gp), "r"(mbar) : "memory");
            } else {
                asm volatile("mbarrier.arrive.expect_tx.shared.b64 _, [%0], 96;"
                             :: "r"(mbar) : "memory");
                uint64_t gp = __cvta_generic_to_global(locG + (size_t)mrow * 24);
                asm volatile(
                    "cp.async.bulk.shared::cluster.global.mbarrier::complete_tx::bytes "
                    "[%0], [%1], 96, [%2];"
                    :: "r"(dst), "l"(gp), "r"(mbar) : "memory");
            }
        }
    };

    float acc[4][4];
    #pragma unroll
    for (int b = 0; b < 4; b++)
        acc[b][0] = acc[b][1] = acc[b][2] = acc[b][3] = 0.f;

    stage(0, 0);

    for (int c = 0; c < NCHUNK; c++) {
        if (c + 1 < NCHUNK) stage(c + 1, (c + 1) & 1);

        mbar_wait(sbase + OFF_MBAR + (c & 1) * 8, (c >> 1) & 1);

        const char* A = smem + ((c & 1) ? OFF_A1 : OFF_A0);
        const char* aRow0 = A + (wr * 16 + gq) * ROWB + gr * 4;
        const float2* bG = g_fragW + c * 2048 + wc * 1024 + lane;

        const int ksteps = (c < 10) ? 8 : 3;
        #pragma unroll 4
        for (int ks = 0; ks < ksteps; ks++) {
            const int o = ks * 32;
            uint32_t a0 = tf32u(*(const float*)(aRow0 + o));
            uint32_t a1 = tf32u(*(const float*)(aRow0 + 8 * ROWB + o));
            uint32_t a2 = tf32u(*(const float*)(aRow0 + o + 16));
            uint32_t a3 = tf32u(*(const float*)(aRow0 + 8 * ROWB + o + 16));
            #pragma unroll
            for (int nt = 0; nt < 4; nt++) {
                float2 b = __ldg(bG + (nt * 8 + ks) * 32);
                uint32_t b0 = __float_as_uint(b.x), b1 = __float_as_uint(b.y);
                mma_tf32(acc[nt], a0, a1, a2, a3, b0, b1);
            }
        }
        __syncthreads();   // all warps done reading buf (c&1) before it is restaged
    }

    // ---- epilogue: bounce through smem (stride 68 floats) ----
    float* sO = (float*)smem;
    #pragma unroll
    for (int nt = 0; nt < 4; nt++) {
        int row = wr * 16 + gq;
        int col = wc * 32 + nt * 8 + gr * 2;
        sO[row * 68 + col]           = acc[nt][0];
        sO[row * 68 + col + 1]       = acc[nt][1];
        sO[(row + 8) * 68 + col]     = acc[nt][2];
        sO[(row + 8) * 68 + col + 1] = acc[nt][3];
    }
    __syncthreads();

    float2 bb = *(const float2*)(bias + lane * 2);
    float* O = out + (size_t)g * MPTS * OUTC;
    for (int r = wid; r < BM; r += 16) {
        int m = m0 + r;
        if (m < MPTS) {
            float2 v = *(float2*)(sO + r * 68 + lane * 2);
            v.x = fmaxf(v.x + bb.x, 0.f);
            v.y = fmaxf(v.y + bb.y, 0.f);
            *(float2*)(O + (size_t)m * OUTC + lane * 2) = v;
        }
    }
}

extern "C" void kernel_launch(void* const* d_in, const int* in_sizes, int n_in,
                              void* d_out, int out_size)
{
    const float* feats = (const float*)d_in[0];
    const int*   aff   = (const int*)  d_in[1];
    const float* locs  = (const float*)d_in[2];
    const float* Wt    = (const float*)d_in[3];
    const float* bias  = (const float*)d_in[4];
    float*       out   = (float*)d_out;

    k_prep<<<NB_LOC + NB_FRG, NTH>>>(aff, locs, Wt);

    cudaFuncSetAttribute(affconv_main,
                         cudaFuncAttributeMaxDynamicSharedMemorySize, SMEM_MAIN);
    dim3 grid((MPTS + BM - 1) / BM, NG);
    affconv_main<<<grid, NTHM, SMEM_MAIN>>>(feats, aff, bias, out);
}

// round 17
// speedup vs baseline: 1.1522x; 1.1522x over previous
#include <cuda_runtime.h>
#include <cstdint>

#define NG    4
#define MPTS  50000
#define CIN   64
#define KNN   9
#define OUTC  64
#define BM    128
#define NTH   256
#define NCHUNK 11

#define ROWB      272
#define A_BYTES   (BM * ROWB)
#define OFF_A0    0
#define OFF_A1    A_BYTES
#define OFF_IDX   (2 * A_BYTES)
#define OFF_MBAR  (OFF_IDX + BM * KNN * 4)
#define SMEM_MAIN (OFF_MBAR + 16)            // 74256 -> 3 CTAs/SM

// prepass block ranges (conv pass eliminated)
#define NB_LOC  782                          // ceil(200000/256)
#define NB_FRG  88                           // 11*2048/256

// ---- persistent scratch ----
__device__ float  g_locF[(size_t)NG * MPTS * 24];      // precomputed loc features (tf32-rna)
__device__ float2 g_fragW[NCHUNK * 2048];              // W in b-fragment order (tf32-rna)

__device__ __forceinline__ float tf32r(float x) {
    uint32_t u;
    asm("cvt.rna.tf32.f32 %0, %1;" : "=r"(u) : "f"(x));
    return __uint_as_float(u);
}
__device__ __forceinline__ uint32_t tf32u(float x) {
    uint32_t u;
    asm("cvt.rna.tf32.f32 %0, %1;" : "=r"(u) : "f"(x));
    return u;
}
__device__ __forceinline__ uint32_t smem_u32(const void* p) {
    uint32_t a;
    asm("{ .reg .u64 t; cvta.to.shared.u64 t, %1; cvt.u32.u64 %0, t; }" : "=r"(a) : "l"(p));
    return a;
}
__device__ __forceinline__ void mma_tf32(float d[4],
                                         uint32_t a0, uint32_t a1, uint32_t a2, uint32_t a3,
                                         uint32_t b0, uint32_t b1) {
    asm volatile(
        "mma.sync.aligned.m16n8k8.row.col.f32.tf32.tf32.f32 "
        "{%0,%1,%2,%3}, {%4,%5,%6,%7}, {%8,%9}, {%0,%1,%2,%3};"
        : "+f"(d[0]), "+f"(d[1]), "+f"(d[2]), "+f"(d[3])
        : "r"(a0), "r"(a1), "r"(a2), "r"(a3), "r"(b0), "r"(b1));
}
__device__ __forceinline__ void mbar_wait(uint32_t mbar, uint32_t parity) {
    uint32_t done;
    asm volatile(
        "{\n\t.reg .pred p;\n\t"
        "mbarrier.try_wait.parity.acquire.cta.shared::cta.b64 p, [%1], %2;\n\t"
        "selp.b32 %0, 1, 0, p;\n\t}"
        : "=r"(done) : "r"(mbar), "r"(parity) : "memory");
    if (!done) {
        asm volatile(
            "{\n\t.reg .pred P1;\n\t"
            "W_%=:\n\t"
            "mbarrier.try_wait.parity.acquire.cta.shared::cta.b64 P1, [%0], %1, 0x989680;\n\t"
            "@P1 bra.uni D_%=;\n\t"
            "bra.uni W_%=;\n\t"
            "D_%=:\n\t}"
            :: "r"(mbar), "r"(parity) : "memory");
    }
}

// ---------------- small pre-pass (loc features + W fragments only) ----------------

__global__ void __launch_bounds__(NTH) k_prep(const int*   __restrict__ aff,
                                              const float* __restrict__ locs,
                                              const float* __restrict__ Wt)
{
    int b = blockIdx.x;
    if (b < NB_LOC) {
        int t = b * NTH + threadIdx.x;
        if (t >= NG * MPTS) return;
        int g = t / MPTS, m = t - g * MPTS;
        const int*   I = aff  + (size_t)g * MPTS * KNN + (size_t)m * KNN;
        const float* L = locs + (size_t)g * MPTS * 2;
        float lx = L[2 * m], ly = L[2 * m + 1];
        float o[24];
        #pragma unroll
        for (int j = 18; j < 24; j++) o[j] = 0.f;
        #pragma unroll
        for (int k = 0; k < KNN; k++) {
            int s = I[k];
            float dx = (L[2 * s]     - lx) * (1.0f / 11.0f);
            float dy = (L[2 * s + 1] - ly) * (1.0f / 11.0f);
            o[2 * k]     = tf32r(fminf(fmaxf(dx, -1.f), 1.f));
            o[2 * k + 1] = tf32r(fminf(fmaxf(dy, -1.f), 1.f));
        }
        float4* d = (float4*)(g_locF + (size_t)t * 24);
        #pragma unroll
        for (int j = 0; j < 6; j++)
            d[j] = make_float4(o[4*j], o[4*j+1], o[4*j+2], o[4*j+3]);
        return;
    }
    b -= NB_LOC;
    {
        int t = b * NTH + threadIdx.x;
        if (t >= NCHUNK * 2048) return;
        int c = t / 2048, rem = t % 2048;
        int nt = rem >> 8, ks = (rem >> 5) & 7, ln = rem & 31;
        int gq = ln >> 2, gr = ln & 3;
        int col = nt * 8 + gq;
        int k0 = ks * 8 + gr;
        int k1 = k0 + 4;
        auto krow = [&](int k) -> int {
            if (c < 9)  return c * 66 + 2 + k;
            if (c == 9) return 594 + k;
            return (k < 18) ? (k >> 1) * 66 + (k & 1) : -1;
        };
        int r0 = krow(k0), r1 = krow(k1);
        float v0 = (r0 >= 0) ? tf32r(Wt[(size_t)r0 * OUTC + col]) : 0.f;
        float v1 = (r1 >= 0) ? tf32r(Wt[(size_t)r1 * OUTC + col]) : 0.f;
        g_fragW[t] = make_float2(v0, v1);
    }
}

// ---------------- main kernel (best-known artifact: R9/R14, byte-exact) ----------------

extern "C" __global__ void __launch_bounds__(NTH, 3)
affconv_main(const float* __restrict__ feats,
             const int*   __restrict__ aff,
             const float* __restrict__ bias,
             float* __restrict__ out)
{
    extern __shared__ char smem[];
    const uint32_t sbase = smem_u32(smem);
    const int tid = threadIdx.x, lane = tid & 31, wid = tid >> 5;
    const int g = blockIdx.y, m0 = blockIdx.x * BM;
    const int gq = lane >> 2, gr = lane & 3;
    const int wr = wid >> 1, wc = wid & 1;          // 4x2 warp grid

    int* sIdx = (int*)(smem + OFF_IDX);
    const int* I = aff + (size_t)g * MPTS * KNN;

    if (tid == 0) {
        asm volatile("mbarrier.init.shared.b64 [%0], %1;" :: "r"(sbase + OFF_MBAR),     "r"(128u) : "memory");
        asm volatile("mbarrier.init.shared.b64 [%0], %1;" :: "r"(sbase + OFF_MBAR + 8), "r"(128u) : "memory");
    }
    for (int i = tid; i < BM * KNN; i += NTH) {
        int r = i / KNN, c = i - r * KNN;
        int m = m0 + r; if (m >= MPTS) m = MPTS - 1;
        sIdx[i] = I[(size_t)m * KNN + c];
    }
    __syncthreads();

    int mrow = m0 + tid; if (mrow >= MPTS) mrow = MPTS - 1;   // valid for tid<128
    const float* featG = feats  + (size_t)g * MPTS * CIN;     // RAW feats (rna applied in-loop)
    const float* locG  = g_locF + (size_t)g * MPTS * 24;

    auto stage = [&](int c, int buf) {
        if (tid < BM) {
            uint32_t mbar = sbase + OFF_MBAR + buf * 8;
            uint32_t dst  = sbase + (buf ? OFF_A1 : OFF_A0) + tid * ROWB;
            if (c < 10) {
                asm volatile("mbarrier.arrive.expect_tx.shared.b64 _, [%0], 256;"
                             :: "r"(mbar) : "memory");
                int src = (c < 9) ? sIdx[tid * KNN + c] : mrow;
                uint64_t gp = __cvta_generic_to_global(featG + (size_t)src * CIN);
                asm volatile(
                    "cp.async.bulk.shared::cluster.global.mbarrier::complete_tx::bytes "
                    "[%0], [%1], 256, [%2];"
                    :: "r"(dst), "l"(gp), "r"(mbar) : "memory");
            } else {
                asm volatile("mbarrier.arrive.expect_tx.shared.b64 _, [%0], 96;"
                             :: "r"(mbar) : "memory");
                uint64_t gp = __cvta_generic_to_global(locG + (size_t)mrow * 24);
                asm volatile(
                    "cp.async.bulk.shared::cluster.global.mbarrier::complete_tx::bytes "
                    "[%0], [%1], 96, [%2];"
                    :: "r"(dst), "l"(gp), "r"(mbar) : "memory");
            }
        }
    };

    float acc[2][4][4];
    #pragma unroll
    for (int a = 0; a < 2; a++)
        #pragma unroll
        for (int b = 0; b < 4; b++)
            acc[a][b][0] = acc[a][b][1] = acc[a][b][2] = acc[a][b][3] = 0.f;

    stage(0, 0);

    for (int c = 0; c < NCHUNK; c++) {
        if (c + 1 < NCHUNK) stage(c + 1, (c + 1) & 1);

        mbar_wait(sbase + OFF_MBAR + (c & 1) * 8, (c >> 1) & 1);

        const char* A = smem + ((c & 1) ? OFF_A1 : OFF_A0);
        const char* aRow0 = A + (wr * 32 + gq) * ROWB + gr * 4;
        const float2* bG = g_fragW + c * 2048 + wc * 1024 + lane;

        const int ksteps = (c < 10) ? 8 : 3;
        #pragma unroll 4
        for (int ks = 0; ks < ksteps; ks++) {
            const int o = ks * 32;
            uint32_t a00 = tf32u(*(const float*)(aRow0 + o));
            uint32_t a01 = tf32u(*(const float*)(aRow0 + 8 * ROWB + o));
            uint32_t a02 = tf32u(*(const float*)(aRow0 + o + 16));
            uint32_t a03 = tf32u(*(const float*)(aRow0 + 8 * ROWB + o + 16));
            uint32_t a10 = tf32u(*(const float*)(aRow0 + 16 * ROWB + o));
            uint32_t a11 = tf32u(*(const float*)(aRow0 + 24 * ROWB + o));
            uint32_t a12 = tf32u(*(const float*)(aRow0 + 16 * ROWB + o + 16));
            uint32_t a13 = tf32u(*(const float*)(aRow0 + 24 * ROWB + o + 16));
            #pragma unroll
            for (int nt = 0; nt < 4; nt++) {
                float2 b = __ldg(bG + (nt * 8 + ks) * 32);
                uint32_t b0 = __float_as_uint(b.x), b1 = __float_as_uint(b.y);
                mma_tf32(acc[0][nt], a00, a01, a02, a03, b0, b1);
                mma_tf32(acc[1][nt], a10, a11, a12, a13, b0, b1);
            }
        }
        __syncthreads();   // all warps done reading buf (c&1) before it is restaged
    }

    // ---- epilogue: bounce through smem (stride 68 floats) ----
    float* sO = (float*)smem;
    #pragma unroll
    for (int rg = 0; rg < 2; rg++) {
        #pragma unroll
        for (int nt = 0; nt < 4; nt++) {
            int row = wr * 32 + rg * 16 + gq;
            int col = wc * 32 + nt * 8 + gr * 2;
            sO[row * 68 + col]           = acc[rg][nt][0];
            sO[row * 68 + col + 1]       = acc[rg][nt][1];
            sO[(row + 8) * 68 + col]     = acc[rg][nt][2];
            sO[(row + 8) * 68 + col + 1] = acc[rg][nt][3];
        }
    }
    __syncthreads();

    float2 bb = *(const float2*)(bias + lane * 2);
    float* O = out + (size_t)g * MPTS * OUTC;
    for (int r = wid; r < BM; r += 8) {
        int m = m0 + r;
        if (m < MPTS) {
            float2 v = *(float2*)(sO + r * 68 + lane * 2);
            v.x = fmaxf(v.x + bb.x, 0.f);
            v.y = fmaxf(v.y + bb.y, 0.f);
            *(float2*)(O + (size_t)m * OUTC + lane * 2) = v;
        }
    }
}

extern "C" void kernel_launch(void* const* d_in, const int* in_sizes, int n_in,
                              void* d_out, int out_size)
{
    const float* feats = (const float*)d_in[0];
    const int*   aff   = (const int*)  d_in[1];
    const float* locs  = (const float*)d_in[2];
    const float* Wt    = (const float*)d_in[3];
    const float* bias  = (const float*)d_in[4];
    float*       out   = (float*)d_out;

    k_prep<<<NB_LOC + NB_FRG, NTH>>>(aff, locs, Wt);

    cudaFuncSetAttribute(affconv_main,
                         cudaFuncAttributeMaxDynamicSharedMemorySize, SMEM_MAIN);
    dim3 grid((MPTS + BM - 1) / BM, NG);
    affconv_main<<<grid, NTH, SMEM_MAIN>>>(feats, aff, bias, out);
}